// round 13
// baseline (speedup 1.0000x reference)
#include <cuda_runtime.h>
#include <cuda_fp16.h>
#include <cstdint>

// Problem dims
#define B_DIM  4096
#define KDIM   2048   // IN + HID
#define HID_D  1024
#define NTOT   5120   // 3*HID (gates) + HID (cand) + HID (s)

// GEMM tiling
#define TILE_M 256
#define TILE_N 128
#define BK     64
#define NK     (KDIM / BK)      // 32 k-chunks
#define STAGES 3
#define NTHREADS 512

// smem: rows padded to 72 halves (144 B) -> conflict-free ldmatrix (bank start 4r mod 32)
#define LDS_H      72
#define A_BYTES    (TILE_M * LDS_H * 2)       // 36864
#define B_BYTES    (TILE_N * LDS_H * 2)       // 18432
#define STAGE_B    (A_BYTES + B_BYTES)        // 55296
#define SMEM_TOTAL (STAGES * STAGE_B)         // 165888 (1 CTA/SM, 16 warps)

// Scratch (device globals: allocation-free)
__device__ __align__(16) __half g_A[(size_t)B_DIM * KDIM];   // 16 MB fp16
__device__ __align__(16) __half g_W[(size_t)NTOT * KDIM];    // 20 MB fp16
__device__ __align__(16) __half g_C[(size_t)B_DIM * NTOT];   // 40 MB fp16

// ---------------- PTX helpers ----------------
__device__ __forceinline__ uint32_t smem_u32(const void* p) {
    uint32_t a;
    asm("{ .reg .u64 t; cvta.to.shared.u64 t, %1; cvt.u32.u64 %0, t; }"
        : "=r"(a) : "l"(p));
    return a;
}

__device__ __forceinline__ void cp16(uint32_t d, const void* s) {
    asm volatile("cp.async.cg.shared.global [%0], [%1], 16;" :: "r"(d), "l"(s));
}
#define CP_COMMIT() asm volatile("cp.async.commit_group;" ::: "memory")
#define CP_WAIT(n)  asm volatile("cp.async.wait_group %0;" :: "n"(n) : "memory")

__device__ __forceinline__ void ldsm4(uint32_t* r, uint32_t addr) {
    asm volatile("ldmatrix.sync.aligned.m8n8.x4.shared.b16 {%0,%1,%2,%3}, [%4];"
                 : "=r"(r[0]), "=r"(r[1]), "=r"(r[2]), "=r"(r[3]) : "r"(addr));
}

__device__ __forceinline__ void mma16816(float* c, const uint32_t* a,
                                         uint32_t b0, uint32_t b1) {
    asm volatile(
        "mma.sync.aligned.m16n8k16.row.col.f32.f16.f16.f32 "
        "{%0,%1,%2,%3}, {%4,%5,%6,%7}, {%8,%9}, {%0,%1,%2,%3};"
        : "+f"(c[0]), "+f"(c[1]), "+f"(c[2]), "+f"(c[3])
        : "r"(a[0]), "r"(a[1]), "r"(a[2]), "r"(a[3]), "r"(b0), "r"(b1));
}

// ---------------- pack kernels ----------------
__global__ void __launch_bounds__(256) pack_a_kernel(const float* __restrict__ x,
                                                     const float* __restrict__ h) {
    int idx = blockIdx.x * blockDim.x + threadIdx.x;   // 0 .. B*K/4-1
    int b = idx >> 9;
    int k = (idx & 511) << 2;
    float4 v = (k < 1024)
        ? *(const float4*)(x + (size_t)b * 1024 + k)
        : *(const float4*)(h + (size_t)b * 1024 + (k - 1024));
    __half2* dst = (__half2*)(g_A + (size_t)b * KDIM + k);
    dst[0] = __floats2half2_rn(v.x, v.y);
    dst[1] = __floats2half2_rn(v.z, v.w);
}

__global__ void __launch_bounds__(256) pack_w_kernel(
    const float* __restrict__ Wi, const float* __restrict__ Wf,
    const float* __restrict__ Wo, const float* __restrict__ Wxg,
    const float* __restrict__ Whg, const float* __restrict__ Wxs) {
    int idx = blockIdx.x * blockDim.x + threadIdx.x;   // 0 .. NTOT*K/4-1
    int r = idx >> 9;
    int k = (idx & 511) << 2;
    float4 v;
    if (r < 3072) {
        const float* W = (r < 1024) ? Wi : (r < 2048 ? Wf : Wo);
        int rr = r & 1023;
        v = *(const float4*)(W + (size_t)rr * 2048 + k);
    } else if (r < 4096) {
        int rr = r - 3072;
        v = (k < 1024) ? *(const float4*)(Wxg + (size_t)rr * 1024 + k)
                       : *(const float4*)(Whg + (size_t)rr * 1024 + (k - 1024));
    } else {
        int rr = r - 4096;
        v = (k < 1024) ? *(const float4*)(Wxs + (size_t)rr * 1024 + k)
                       : make_float4(0.f, 0.f, 0.f, 0.f);
    }
    __half2* dst = (__half2*)(g_W + (size_t)r * KDIM + k);
    dst[0] = __floats2half2_rn(v.x, v.y);
    dst[1] = __floats2half2_rn(v.z, v.w);
}

// ---------------- GEMM kernel (mma.sync m16n8k16, 256x128 tile, BK=64) ----------------
__device__ __forceinline__ void load_stage(uint32_t sb, int st, int kc,
                                           int m0, int n0, int tid) {
    const uint32_t base = sb + st * STAGE_B;
    const int k0 = kc * BK;
    // A: 256 rows x 8 segs(16B) = 2048 cp16
    #pragma unroll
    for (int i = 0; i < 4; ++i) {
        int c = tid + i * NTHREADS;
        int row = c >> 3, seg = c & 7;
        cp16(base + row * 144 + seg * 16,
             g_A + (size_t)(m0 + row) * KDIM + k0 + seg * 8);
    }
    // B: 128 rows x 8 segs = 1024 cp16
    #pragma unroll
    for (int i = 0; i < 2; ++i) {
        int c = tid + i * NTHREADS;
        int row = c >> 3, seg = c & 7;
        cp16(base + A_BYTES + row * 144 + seg * 16,
             g_W + (size_t)(n0 + row) * KDIM + k0 + seg * 8);
    }
}

__global__ void __launch_bounds__(NTHREADS, 1) gemm_kernel() {
    extern __shared__ char smem[];
    const uint32_t sb = smem_u32(smem);
    const int tid  = threadIdx.x;
    const int lane = tid & 31;
    const int wid  = tid >> 5;
    const int m0 = blockIdx.x * TILE_M;
    const int n0 = blockIdx.y * TILE_N;
    const int wm = (wid & 3) * 64;        // 4 warps along M, warp tile 64 x 32
    const int wn = (wid >> 2) * 32;       // 4 warps along N

    // s-slab (rows >= 4096 of packed W) has zero top half of K: skip it
    const int NKloc = (n0 >= 4096) ? (NK / 2) : NK;

    float acc[4][4][4];
    #pragma unroll
    for (int i = 0; i < 4; ++i)
        #pragma unroll
        for (int j = 0; j < 4; ++j)
            #pragma unroll
            for (int q = 0; q < 4; ++q) acc[i][j][q] = 0.f;

    // prologue: fill STAGES-1 = 2 stages
    #pragma unroll
    for (int st = 0; st < STAGES - 1; ++st) {
        load_stage(sb, st, st, m0, n0, tid);
        CP_COMMIT();
    }

    // precomputed ldmatrix indices (relative to stage base)
    const int arow = wm + (lane & 15);
    const int acol0 = (lane >> 4) * 8;
    const int g = lane >> 3;
    const int brow = wn + (g >> 1) * 8 + (lane & 7);
    const int bcol0 = (g & 1) * 8;

    for (int kt = 0; kt < NKloc; ++kt) {
        CP_WAIT(STAGES - 2);              // stage kt%STAGES ready
        __syncthreads();
        if (kt + STAGES - 1 < NKloc)
            load_stage(sb, (kt + STAGES - 1) % STAGES, kt + STAGES - 1, m0, n0, tid);
        CP_COMMIT();                      // unconditional: keeps group count fixed

        const uint32_t sA = sb + (kt % STAGES) * STAGE_B;
        const uint32_t sB = sA + A_BYTES;
        #pragma unroll
        for (int s = 0; s < 4; ++s) {     // four k16 substeps per BK=64
            const int kk = s * 16;
            uint32_t a[4][4], b[2][4];
            #pragma unroll
            for (int mf = 0; mf < 4; ++mf)
                ldsm4(a[mf], sA + (uint32_t)((arow + mf * 16) * LDS_H + kk + acol0) * 2);
            #pragma unroll
            for (int h = 0; h < 2; ++h)
                ldsm4(b[h], sB + (uint32_t)((brow + h * 16) * LDS_H + kk + bcol0) * 2);
            #pragma unroll
            for (int mf = 0; mf < 4; ++mf)
                #pragma unroll
                for (int nf = 0; nf < 4; ++nf)
                    mma16816(acc[mf][nf], a[mf],
                             b[nf >> 1][(nf & 1) * 2], b[nf >> 1][(nf & 1) * 2 + 1]);
        }
    }

    // write accumulators to g_C (fp16)
    #pragma unroll
    for (int mf = 0; mf < 4; ++mf) {
        #pragma unroll
        for (int nf = 0; nf < 4; ++nf) {
            const int m = m0 + wm + mf * 16 + (lane >> 2);
            const int n = n0 + wn + nf * 8 + (lane & 3) * 2;
            __half* p = g_C + (size_t)m * NTOT + n;
            *(__half2*)p = __floats2half2_rn(acc[mf][nf][0], acc[mf][nf][1]);
            *(__half2*)(p + (size_t)8 * NTOT) =
                __floats2half2_rn(acc[mf][nf][2], acc[mf][nf][3]);
        }
    }
}

// ---------------- elementwise epilogue ----------------
__device__ __forceinline__ float sigm(float z) { return 1.f / (1.f + __expf(-z)); }

__device__ __forceinline__ float4 ld4h(const __half* p) {
    uint2 raw = *(const uint2*)p;              // 4 halves, 8B aligned
    float2 lo = __half22float2(*(__half2*)&raw.x);
    float2 hi = __half22float2(*(__half2*)&raw.y);
    return make_float4(lo.x, lo.y, hi.x, hi.y);
}

__global__ void __launch_bounds__(256) epilogue_kernel(
    const float* __restrict__ c_prev,
    const float* __restrict__ bi, const float* __restrict__ bf_,
    const float* __restrict__ bo, const float* __restrict__ bxs,
    const float* __restrict__ bxg, const float* __restrict__ bhg,
    float* __restrict__ out) {
    int idx = blockIdx.x * blockDim.x + threadIdx.x;   // 0 .. B*HID/4-1
    int b = idx >> 8;
    int j = (idx & 255) << 2;
    const __half* base = g_C + (size_t)b * NTOT;
    float4 zi = ld4h(base + j);
    float4 zf = ld4h(base + 1024 + j);
    float4 zo = ld4h(base + 2048 + j);
    float4 zg = ld4h(base + 3072 + j);
    float4 zs = ld4h(base + 4096 + j);
    float4 vbi  = *(const float4*)(bi + j);
    float4 vbf  = *(const float4*)(bf_ + j);
    float4 vbo  = *(const float4*)(bo + j);
    float4 vbs  = *(const float4*)(bxs + j);
    float4 vbg1 = *(const float4*)(bxg + j);
    float4 vbg2 = *(const float4*)(bhg + j);
    float4 cp = *(const float4*)(c_prev + (size_t)b * 1024 + j);
    float4 hv, cv;
#define CELL(X) {                                                  \
        float it = sigm(zi.X + vbi.X);                             \
        float ft = sigm(zf.X + vbf.X);                             \
        float ot = sigm(zo.X + vbo.X);                             \
        float gg = tanhf((zs.X + vbs.X) * (zg.X + vbg1.X + vbg2.X)); \
        cv.X = ft * cp.X + it * gg;                                \
        hv.X = ot * tanhf(cv.X); }
    CELL(x) CELL(y) CELL(z) CELL(w)
#undef CELL
    *(float4*)(out + (size_t)b * 1024 + j) = hv;
    *(float4*)(out + (size_t)4194304 + (size_t)b * 1024 + j) = cv;
}

// ---------------- launch ----------------
extern "C" void kernel_launch(void* const* d_in, const int* in_sizes, int n_in,
                              void* d_out, int out_size) {
    const float* x   = (const float*)d_in[0];
    const float* h   = (const float*)d_in[1];
    const float* cp  = (const float*)d_in[2];
    const float* Wi  = (const float*)d_in[3];
    const float* bi  = (const float*)d_in[4];
    const float* Wf  = (const float*)d_in[5];
    const float* bf  = (const float*)d_in[6];
    const float* Wo  = (const float*)d_in[7];
    const float* bo  = (const float*)d_in[8];
    const float* Wxs = (const float*)d_in[9];
    const float* bxs = (const float*)d_in[10];
    const float* Wxg = (const float*)d_in[11];
    const float* bxg = (const float*)d_in[12];
    const float* Whg = (const float*)d_in[13];
    const float* bhg = (const float*)d_in[14];

    pack_a_kernel<<<8192, 256>>>(x, h);
    pack_w_kernel<<<10240, 256>>>(Wi, Wf, Wo, Wxg, Whg, Wxs);
    cudaFuncSetAttribute(gemm_kernel, cudaFuncAttributeMaxDynamicSharedMemorySize,
                         SMEM_TOTAL);
    gemm_kernel<<<dim3(B_DIM / TILE_M, NTOT / TILE_N), NTHREADS, SMEM_TOTAL>>>();
    epilogue_kernel<<<4096, 256>>>(cp, bi, bf, bo, bxs, bxg, bhg, (float*)d_out);
}

// round 14
// speedup vs baseline: 1.0526x; 1.0526x over previous
#include <cuda_runtime.h>
#include <cuda_fp16.h>
#include <cstdint>

// Problem dims
#define B_DIM  4096
#define KDIM   2048   // IN + HID
#define HID_D  1024
#define NTOT   5120   // 3*HID (gates) + HID (cand) + HID (s)

// GEMM tiling (R11 proven config)
#define TILE_M 128
#define TILE_N 128
#define BK     64
#define NK     (KDIM / BK)      // 32 k-chunks
#define STAGES 3

// smem: rows padded to 72 halves (144 B) -> conflict-free ldmatrix (bank start 4r mod 32)
#define LDS_H      72
#define A_BYTES    (TILE_M * LDS_H * 2)       // 18432
#define B_BYTES    (TILE_N * LDS_H * 2)       // 18432
#define STAGE_B    (A_BYTES + B_BYTES)        // 36864
#define SMEM_TOTAL (STAGES * STAGE_B)         // 110592 -> 2 CTAs/SM

// Scratch (device globals: allocation-free)
__device__ __align__(16) __half g_A[(size_t)B_DIM * KDIM];   // 16 MB fp16
__device__ __align__(16) __half g_W[(size_t)NTOT * KDIM];    // 20 MB fp16
__device__ __align__(16) __half g_C[(size_t)B_DIM * NTOT];   // 40 MB fp16

// ---------------- PTX helpers ----------------
__device__ __forceinline__ uint32_t smem_u32(const void* p) {
    uint32_t a;
    asm("{ .reg .u64 t; cvta.to.shared.u64 t, %1; cvt.u32.u64 %0, t; }"
        : "=r"(a) : "l"(p));
    return a;
}

__device__ __forceinline__ void cp16(uint32_t d, const void* s) {
    asm volatile("cp.async.cg.shared.global [%0], [%1], 16;" :: "r"(d), "l"(s));
}
#define CP_COMMIT() asm volatile("cp.async.commit_group;" ::: "memory")
#define CP_WAIT(n)  asm volatile("cp.async.wait_group %0;" :: "n"(n) : "memory")

__device__ __forceinline__ void ldsm4(uint32_t* r, uint32_t addr) {
    asm volatile("ldmatrix.sync.aligned.m8n8.x4.shared.b16 {%0,%1,%2,%3}, [%4];"
                 : "=r"(r[0]), "=r"(r[1]), "=r"(r[2]), "=r"(r[3]) : "r"(addr));
}

__device__ __forceinline__ void mma16816(float* c, const uint32_t* a,
                                         uint32_t b0, uint32_t b1) {
    asm volatile(
        "mma.sync.aligned.m16n8k16.row.col.f32.f16.f16.f32 "
        "{%0,%1,%2,%3}, {%4,%5,%6,%7}, {%8,%9}, {%0,%1,%2,%3};"
        : "+f"(c[0]), "+f"(c[1]), "+f"(c[2]), "+f"(c[3])
        : "r"(a[0]), "r"(a[1]), "r"(a[2]), "r"(a[3]), "r"(b0), "r"(b1));
}

// ---------------- fused pack kernel ----------------
// blocks [0, 8192): A pack; blocks [8192, 18432): W pack
__global__ void __launch_bounds__(256) pack_kernel(
    const float* __restrict__ x,   const float* __restrict__ h,
    const float* __restrict__ Wi,  const float* __restrict__ Wf,
    const float* __restrict__ Wo,  const float* __restrict__ Wxg,
    const float* __restrict__ Whg, const float* __restrict__ Wxs) {
    if (blockIdx.x < 8192) {
        int idx = blockIdx.x * 256 + threadIdx.x;      // 0 .. B*K/4-1
        int b = idx >> 9;
        int k = (idx & 511) << 2;
        float4 v = (k < 1024)
            ? *(const float4*)(x + (size_t)b * 1024 + k)
            : *(const float4*)(h + (size_t)b * 1024 + (k - 1024));
        __half2* dst = (__half2*)(g_A + (size_t)b * KDIM + k);
        dst[0] = __floats2half2_rn(v.x, v.y);
        dst[1] = __floats2half2_rn(v.z, v.w);
    } else {
        int idx = (blockIdx.x - 8192) * 256 + threadIdx.x;  // 0 .. NTOT*K/4-1
        int r = idx >> 9;
        int k = (idx & 511) << 2;
        float4 v;
        if (r < 3072) {
            const float* W = (r < 1024) ? Wi : (r < 2048 ? Wf : Wo);
            int rr = r & 1023;
            v = *(const float4*)(W + (size_t)rr * 2048 + k);
        } else if (r < 4096) {
            int rr = r - 3072;
            v = (k < 1024) ? *(const float4*)(Wxg + (size_t)rr * 1024 + k)
                           : *(const float4*)(Whg + (size_t)rr * 1024 + (k - 1024));
        } else {
            int rr = r - 4096;
            v = (k < 1024) ? *(const float4*)(Wxs + (size_t)rr * 1024 + k)
                           : make_float4(0.f, 0.f, 0.f, 0.f);
        }
        __half2* dst = (__half2*)(g_W + (size_t)r * KDIM + k);
        dst[0] = __floats2half2_rn(v.x, v.y);
        dst[1] = __floats2half2_rn(v.z, v.w);
    }
}

// ---------------- GEMM kernel (mma.sync m16n8k16, 128x128 tile, BK=64) ----------------
__device__ __forceinline__ void load_stage(uint32_t sb, int st, int kc,
                                           int m0, int n0, int tid) {
    const uint32_t base = sb + st * STAGE_B;
    const int k0 = kc * BK;
    // A: 128 rows x 8 segs(16B) = 1024 cp16
    #pragma unroll
    for (int i = 0; i < 4; ++i) {
        int c = tid + i * 256;
        int row = c >> 3, seg = c & 7;
        cp16(base + row * 144 + seg * 16,
             g_A + (size_t)(m0 + row) * KDIM + k0 + seg * 8);
    }
    // B: 128 rows x 8 segs = 1024 cp16
    #pragma unroll
    for (int i = 0; i < 4; ++i) {
        int c = tid + i * 256;
        int row = c >> 3, seg = c & 7;
        cp16(base + A_BYTES + row * 144 + seg * 16,
             g_W + (size_t)(n0 + row) * KDIM + k0 + seg * 8);
    }
}

__global__ void __launch_bounds__(256, 2) gemm_kernel() {
    extern __shared__ char smem[];
    const uint32_t sb = smem_u32(smem);
    const int tid  = threadIdx.x;
    const int lane = tid & 31;
    const int wid  = tid >> 5;
    const int m0 = blockIdx.x * TILE_M;
    const int n0 = blockIdx.y * TILE_N;
    const int wm = (wid & 1) * 64;        // 2 warps along M, warp tile 64 x 32
    const int wn = (wid >> 1) * 32;       // 4 warps along N

    // s-slab (rows >= 4096 of packed W) has zero top half of K: skip it
    const int NKloc = (n0 >= 4096) ? (NK / 2) : NK;

    float acc[4][4][4];
    #pragma unroll
    for (int i = 0; i < 4; ++i)
        #pragma unroll
        for (int j = 0; j < 4; ++j)
            #pragma unroll
            for (int q = 0; q < 4; ++q) acc[i][j][q] = 0.f;

    // prologue: fill STAGES-1 = 2 stages
    #pragma unroll
    for (int st = 0; st < STAGES - 1; ++st) {
        load_stage(sb, st, st, m0, n0, tid);
        CP_COMMIT();
    }

    // precomputed ldmatrix indices (relative to stage base)
    const int arow = wm + (lane & 15);
    const int acol0 = (lane >> 4) * 8;
    const int g = lane >> 3;
    const int brow = wn + (g >> 1) * 8 + (lane & 7);
    const int bcol0 = (g & 1) * 8;

    for (int kt = 0; kt < NKloc; ++kt) {
        CP_WAIT(STAGES - 2);              // stage kt%STAGES ready
        __syncthreads();
        if (kt + STAGES - 1 < NKloc)
            load_stage(sb, (kt + STAGES - 1) % STAGES, kt + STAGES - 1, m0, n0, tid);
        CP_COMMIT();                      // unconditional: keeps group count fixed

        const uint32_t sA = sb + (kt % STAGES) * STAGE_B;
        const uint32_t sB = sA + A_BYTES;
        #pragma unroll
        for (int s = 0; s < 4; ++s) {     // four k16 substeps per BK=64
            const int kk = s * 16;
            uint32_t a[4][4], b[2][4];
            #pragma unroll
            for (int mf = 0; mf < 4; ++mf)
                ldsm4(a[mf], sA + (uint32_t)((arow + mf * 16) * LDS_H + kk + acol0) * 2);
            #pragma unroll
            for (int h = 0; h < 2; ++h)
                ldsm4(b[h], sB + (uint32_t)((brow + h * 16) * LDS_H + kk + bcol0) * 2);
            #pragma unroll
            for (int mf = 0; mf < 4; ++mf)
                #pragma unroll
                for (int nf = 0; nf < 4; ++nf)
                    mma16816(acc[mf][nf], a[mf],
                             b[nf >> 1][(nf & 1) * 2], b[nf >> 1][(nf & 1) * 2 + 1]);
        }
    }

    // write accumulators to g_C (fp16)
    #pragma unroll
    for (int mf = 0; mf < 4; ++mf) {
        #pragma unroll
        for (int nf = 0; nf < 4; ++nf) {
            const int m = m0 + wm + mf * 16 + (lane >> 2);
            const int n = n0 + wn + nf * 8 + (lane & 3) * 2;
            __half* p = g_C + (size_t)m * NTOT + n;
            *(__half2*)p = __floats2half2_rn(acc[mf][nf][0], acc[mf][nf][1]);
            *(__half2*)(p + (size_t)8 * NTOT) =
                __floats2half2_rn(acc[mf][nf][2], acc[mf][nf][3]);
        }
    }
}

// ---------------- elementwise epilogue ----------------
__device__ __forceinline__ float sigm(float z) { return 1.f / (1.f + __expf(-z)); }

__device__ __forceinline__ float4 ld4h(const __half* p) {
    uint2 raw = *(const uint2*)p;              // 4 halves, 8B aligned
    float2 lo = __half22float2(*(__half2*)&raw.x);
    float2 hi = __half22float2(*(__half2*)&raw.y);
    return make_float4(lo.x, lo.y, hi.x, hi.y);
}

__global__ void __launch_bounds__(256) epilogue_kernel(
    const float* __restrict__ c_prev,
    const float* __restrict__ bi, const float* __restrict__ bf_,
    const float* __restrict__ bo, const float* __restrict__ bxs,
    const float* __restrict__ bxg, const float* __restrict__ bhg,
    float* __restrict__ out) {
    int idx = blockIdx.x * blockDim.x + threadIdx.x;   // 0 .. B*HID/4-1
    int b = idx >> 8;
    int j = (idx & 255) << 2;
    const __half* base = g_C + (size_t)b * NTOT;
    float4 zi = ld4h(base + j);
    float4 zf = ld4h(base + 1024 + j);
    float4 zo = ld4h(base + 2048 + j);
    float4 zg = ld4h(base + 3072 + j);
    float4 zs = ld4h(base + 4096 + j);
    float4 vbi  = *(const float4*)(bi + j);
    float4 vbf  = *(const float4*)(bf_ + j);
    float4 vbo  = *(const float4*)(bo + j);
    float4 vbs  = *(const float4*)(bxs + j);
    float4 vbg1 = *(const float4*)(bxg + j);
    float4 vbg2 = *(const float4*)(bhg + j);
    float4 cp = *(const float4*)(c_prev + (size_t)b * 1024 + j);
    float4 hv, cv;
#define CELL(X) {                                                  \
        float it = sigm(zi.X + vbi.X);                             \
        float ft = sigm(zf.X + vbf.X);                             \
        float ot = sigm(zo.X + vbo.X);                             \
        float gg = tanhf((zs.X + vbs.X) * (zg.X + vbg1.X + vbg2.X)); \
        cv.X = ft * cp.X + it * gg;                                \
        hv.X = ot * tanhf(cv.X); }
    CELL(x) CELL(y) CELL(z) CELL(w)
#undef CELL
    *(float4*)(out + (size_t)b * 1024 + j) = hv;
    *(float4*)(out + (size_t)4194304 + (size_t)b * 1024 + j) = cv;
}

// ---------------- launch ----------------
extern "C" void kernel_launch(void* const* d_in, const int* in_sizes, int n_in,
                              void* d_out, int out_size) {
    const float* x   = (const float*)d_in[0];
    const float* h   = (const float*)d_in[1];
    const float* cp  = (const float*)d_in[2];
    const float* Wi  = (const float*)d_in[3];
    const float* bi  = (const float*)d_in[4];
    const float* Wf  = (const float*)d_in[5];
    const float* bf  = (const float*)d_in[6];
    const float* Wo  = (const float*)d_in[7];
    const float* bo  = (const float*)d_in[8];
    const float* Wxs = (const float*)d_in[9];
    const float* bxs = (const float*)d_in[10];
    const float* Wxg = (const float*)d_in[11];
    const float* bxg = (const float*)d_in[12];
    const float* Whg = (const float*)d_in[13];
    const float* bhg = (const float*)d_in[14];

    pack_kernel<<<18432, 256>>>(x, h, Wi, Wf, Wo, Wxg, Whg, Wxs);
    cudaFuncSetAttribute(gemm_kernel, cudaFuncAttributeMaxDynamicSharedMemorySize,
                         SMEM_TOTAL);
    gemm_kernel<<<dim3(B_DIM / TILE_M, NTOT / TILE_N), 256, SMEM_TOTAL>>>();
    epilogue_kernel<<<4096, 256>>>(cp, bi, bf, bo, bxs, bxg, bhg, (float*)d_out);
}